// round 1
// baseline (speedup 1.0000x reference)
#include <cuda_runtime.h>

// Scratch (device globals — no allocations allowed)
__device__ float g_k1[2 * 441 * 64];   // [b*441+d][c]
__device__ float g_v [2 * 64 * 441];   // [b*64+c][21*21]

// ---------------------------------------------------------------------------
// Kernel 1: k1 depthwise conv1d (effective 64 taps) + depthwise 3x3 conv for v
// ---------------------------------------------------------------------------
__global__ void prep_kernel(const float* __restrict__ x,
                            const float* __restrict__ wk,
                            const float* __restrict__ bk,
                            const float* __restrict__ wv,
                            const float* __restrict__ bv) {
    int e = blockIdx.x;
    if (e < 882) {
        // k1[b,d,c] = bk[d] + sum_t x[b,t,d] * wk[d, t + 220 - c]
        int b = e / 441, d = e - b * 441;
        __shared__ float xs[64];
        __shared__ float wks[128];   // wk[d, 157..283]
        int t = threadIdx.x;
        if (t < 64) xs[t] = x[(b * 64 + t) * 441 + d];
        if (t < 127) wks[t] = wk[d * 441 + 157 + t];
        __syncthreads();
        if (t < 64) {
            float acc = bk[d];
#pragma unroll
            for (int tt = 0; tt < 64; tt++)
                acc += xs[tt] * wks[tt + 63 - t];   // (tt+220-t) - 157
            g_k1[e * 64 + t] = acc;
        }
    } else {
        // depthwise 3x3 conv, pad 1: v[b,ch,y,x]
        int id = e - 882;              // [0,128)
        int b = id >> 6, ch = id & 63;
        float w[9];
#pragma unroll
        for (int i = 0; i < 9; i++) w[i] = wv[ch * 9 + i];
        float bias = bv[ch];
        const float* xp = x + (b * 64 + ch) * 441;
        for (int p = threadIdx.x; p < 441; p += blockDim.x) {
            int y = p / 21, xx = p - y * 21;
            float acc = bias;
#pragma unroll
            for (int dy = 0; dy < 3; dy++) {
                int yy = y + dy - 1;
                if (yy < 0 || yy >= 21) continue;
#pragma unroll
                for (int dx = 0; dx < 3; dx++) {
                    int xx2 = xx + dx - 1;
                    if (xx2 < 0 || xx2 >= 21) continue;
                    acc += xp[yy * 21 + xx2] * w[dy * 3 + dx];
                }
            }
            g_v[id * 441 + p] = acc;
        }
    }
}

// ---------------------------------------------------------------------------
// Kernel 2: per (b, g, c-half of 32): gather kq -> att1(25x50) -> BN/ReLU ->
//           logits(441x25) -> softmax(d) -> value dot (64 live terms) -> out
// ---------------------------------------------------------------------------
// SMEM layout (floats): w1s 1252 | kqs 1600 | r1 800 | logits 14112 | red 256 | cmax 32 | csum 32
#define SM_FLOATS (1252 + 1600 + 800 + 14112 + 256 + 32 + 32)

__global__ void main_kernel(const float* __restrict__ x,
                            const float* __restrict__ w1,
                            const float* __restrict__ bng,
                            const float* __restrict__ bnb,
                            const float* __restrict__ bnm,
                            const float* __restrict__ bnv,
                            const float* __restrict__ w2,
                            const float* __restrict__ b2,
                            float* __restrict__ out) {
    extern __shared__ float sm[];
    float* w1s    = sm;              // 1250 used (padded to 1252)
    float* kqs    = w1s + 1252;      // 50 x 32
    float* r1     = kqs + 1600;      // 25 x 32 (16B aligned)
    float* logits = r1 + 800;        // 441 x 32
    float* red    = logits + 14112;  // 8 x 32
    float* cmax   = red + 256;       // 32
    float* csum   = cmax + 32;       // 32

    int bid  = blockIdx.x;
    int b    = bid / 50;
    int g    = (bid >> 1) % 25;
    int half = bid & 1;
    int cbase = half * 32;
    int ph = g / 5, pw = g - ph * 5;
    int tid = threadIdx.x;

    // load w1[g]
    for (int i = tid; i < 1250; i += 256) w1s[i] = w1[g * 1250 + i];

    // gather kq[i2][cl]: u = i2*64 + (cbase+cl) -> (s, c, ij)
    for (int idx = tid; idx < 1600; idx += 256) {
        int i2 = idx >> 5, cl = idx & 31;
        int u = i2 * 64 + cbase + cl;
        int s = u / 1600; int rem = u - s * 1600;
        int c = rem / 25; int ij = rem - c * 25;
        int i5 = ij / 5, j5 = ij - i5 * 5;
        int row = 5 * i5 + ph, col = 5 * j5 + pw;
        float v = 0.f;
        if (row < 21 && col < 21) {
            int sp = row * 21 + col;
            v = (s == 0) ? x[(b * 64 + c) * 441 + sp]
                         : g_k1[(b * 441 + sp) * 64 + c];
        }
        kqs[idx] = v;
    }
    __syncthreads();

    // att1 (25 x 32) = w1[g] (25x50) @ kq (50x32), then BN + ReLU
    for (int idx = tid; idx < 800; idx += 256) {
        int o = idx >> 5, cl = idx & 31;
        float acc = 0.f;
#pragma unroll
        for (int i = 0; i < 50; i++) acc += w1s[o * 50 + i] * kqs[i * 32 + cl];
        int go = g * 25 + o;
        float inv = bng[go] * rsqrtf(bnv[go] + 1e-5f);
        acc = (acc - bnm[go]) * inv + bnb[go];
        r1[idx] = fmaxf(acc, 0.f);
    }
    __syncthreads();

    // logits (441 x 32): blocked 4d x 4c, float4 r1 reads
    const float* w2g = w2 + g * 11025;
    const float* b2g = b2 + g * 441;
    for (int item = tid; item < 111 * 8; item += 256) {
        int dg = item >> 3, cg = item & 7;
        int d0 = dg * 4;
        int dk0 = d0, dk1 = min(d0 + 1, 440), dk2 = min(d0 + 2, 440), dk3 = min(d0 + 3, 440);
        float a0x=0,a0y=0,a0z=0,a0w=0, a1x=0,a1y=0,a1z=0,a1w=0;
        float a2x=0,a2y=0,a2z=0,a2w=0, a3x=0,a3y=0,a3z=0,a3w=0;
#pragma unroll 5
        for (int o = 0; o < 25; o++) {
            float4 r = *(const float4*)&r1[o * 32 + cg * 4];
            float v0 = w2g[dk0 * 25 + o];
            float v1 = w2g[dk1 * 25 + o];
            float v2 = w2g[dk2 * 25 + o];
            float v3 = w2g[dk3 * 25 + o];
            a0x += v0*r.x; a0y += v0*r.y; a0z += v0*r.z; a0w += v0*r.w;
            a1x += v1*r.x; a1y += v1*r.y; a1z += v1*r.z; a1w += v1*r.w;
            a2x += v2*r.x; a2y += v2*r.y; a2z += v2*r.z; a2w += v2*r.w;
            a3x += v3*r.x; a3y += v3*r.y; a3z += v3*r.z; a3w += v3*r.w;
        }
        int cc = cg * 4;
        {
            float bb = b2g[dk0];
            float* L = &logits[d0 * 32 + cc];
            L[0] = a0x + bb; L[1] = a0y + bb; L[2] = a0z + bb; L[3] = a0w + bb;
        }
        if (d0 + 1 < 441) {
            float bb = b2g[dk1];
            float* L = &logits[(d0 + 1) * 32 + cc];
            L[0] = a1x + bb; L[1] = a1y + bb; L[2] = a1z + bb; L[3] = a1w + bb;
        }
        if (d0 + 2 < 441) {
            float bb = b2g[dk2];
            float* L = &logits[(d0 + 2) * 32 + cc];
            L[0] = a2x + bb; L[1] = a2y + bb; L[2] = a2z + bb; L[3] = a2w + bb;
        }
        if (d0 + 3 < 441) {
            float bb = b2g[dk3];
            float* L = &logits[(d0 + 3) * 32 + cc];
            L[0] = a3x + bb; L[1] = a3y + bb; L[2] = a3z + bb; L[3] = a3w + bb;
        }
    }
    __syncthreads();

    // softmax over d per c-column (max, then sum of exp)
    {
        int cl = tid & 31, r = tid >> 5;   // 8 rows x 32 cols
        float pm = -1e30f;
        for (int d = r; d < 441; d += 8) pm = fmaxf(pm, logits[d * 32 + cl]);
        red[r * 32 + cl] = pm;
        __syncthreads();
        if (tid < 32) {
            float m = red[tid];
#pragma unroll
            for (int r2 = 1; r2 < 8; r2++) m = fmaxf(m, red[r2 * 32 + tid]);
            cmax[tid] = m;
        }
        __syncthreads();
        float mm = cmax[cl];
        float ps = 0.f;
        for (int d = r; d < 441; d += 8) ps += __expf(logits[d * 32 + cl] - mm);
        __syncthreads();   // red reuse
        red[r * 32 + cl] = ps;
        __syncthreads();
        if (tid < 32) {
            float s2 = 0.f;
#pragma unroll
            for (int r2 = 0; r2 < 8; r2++) s2 += red[r2 * 32 + tid];
            csum[tid] = 1.f / s2;
        }
        __syncthreads();
    }

    // normalize only the live range d in [157, 284) (the only d used below)
    for (int idx = tid; idx < 127 * 32; idx += 256) {
        int d = 157 + (idx >> 5), cl = idx & 31;
        logits[d * 32 + cl] = __expf(logits[d * 32 + cl] - cmax[cl]) * csum[cl];
    }
    __syncthreads();

    // final: for (h,w) with h%5==ph, w%5==pw, h,w in [2,23):
    //   temp = sum_t v[b,t,h-4,w-4] * A[d=220-c+t], out = temp + k1_pad, cropped
    int hl[5], wl[5]; int nh = 0, nw = 0;
    for (int h = ph; h < 23; h += 5) if (h >= 2) hl[nh++] = h;
    for (int w = pw; w < 23; w += 5) if (w >= 2) wl[nw++] = w;
    int npos = nh * nw;
    for (int item = tid; item < npos * 32; item += 256) {
        int p = item >> 5, cl = item & 31;
        int h = hl[p / nw], w = wl[p % nw];
        int c = cbase + cl;
        float acc = 0.f;
        if (h >= 4 && w >= 4) {
            const float* vp = g_v + (b * 64) * 441 + (h - 4) * 21 + (w - 4);
            const float* lp = logits + (220 - c) * 32 + cl;
#pragma unroll 8
            for (int t = 0; t < 64; t++)
                acc += vp[t * 441] * lp[t * 32];
        }
        if (h < 21 && w < 21) acc += g_k1[(b * 441 + h * 21 + w) * 64 + c];
        out[((b * 64 + c) * 21 + (h - 2)) * 21 + (w - 2)] = acc;
    }
}

extern "C" void kernel_launch(void* const* d_in, const int* in_sizes, int n_in,
                              void* d_out, int out_size) {
    const float* x   = (const float*)d_in[0];
    const float* wk  = (const float*)d_in[1];
    const float* bk  = (const float*)d_in[2];
    const float* w1  = (const float*)d_in[3];
    const float* bng = (const float*)d_in[4];
    const float* bnb = (const float*)d_in[5];
    const float* bnm = (const float*)d_in[6];
    const float* bnv = (const float*)d_in[7];
    const float* w2  = (const float*)d_in[8];
    const float* b2  = (const float*)d_in[9];
    const float* wv  = (const float*)d_in[10];
    const float* bv  = (const float*)d_in[11];
    float* out = (float*)d_out;

    cudaFuncSetAttribute(main_kernel, cudaFuncAttributeMaxDynamicSharedMemorySize,
                         SM_FLOATS * (int)sizeof(float));

    prep_kernel<<<1010, 128>>>(x, wk, bk, wv, bv);
    main_kernel<<<100, 256, SM_FLOATS * (int)sizeof(float)>>>(
        x, w1, bng, bnb, bnm, bnv, w2, b2, out);
}

// round 2
// speedup vs baseline: 1.2506x; 1.2506x over previous
#include <cuda_runtime.h>

// Scratch (device globals — no allocations allowed)
__device__ float g_k1[2 * 441 * 64];   // [b*441+d][c]
__device__ float g_v [2 * 64 * 441];   // [b*64+c][21*21]

// ---------------------------------------------------------------------------
// Kernel 1: k1 depthwise conv1d (effective 64 taps) + depthwise 3x3 conv for v
// ---------------------------------------------------------------------------
__global__ void prep_kernel(const float* __restrict__ x,
                            const float* __restrict__ wk,
                            const float* __restrict__ bk,
                            const float* __restrict__ wv,
                            const float* __restrict__ bv) {
    int e = blockIdx.x;
    if (e < 882) {
        // k1[b,d,c] = bk[d] + sum_t x[b,t,d] * wk[d, t + 220 - c]
        int b = e / 441, d = e - b * 441;
        __shared__ float xs[64];
        __shared__ float wks[128];   // wk[d, 157..283]
        int t = threadIdx.x;
        if (t < 64) xs[t] = x[(b * 64 + t) * 441 + d];
        if (t < 127) wks[t] = wk[d * 441 + 157 + t];
        __syncthreads();
        if (t < 64) {
            float acc = bk[d];
#pragma unroll
            for (int tt = 0; tt < 64; tt++)
                acc += xs[tt] * wks[tt + 63 - t];   // (tt+220-t) - 157
            g_k1[e * 64 + t] = acc;
        }
    } else {
        // depthwise 3x3 conv, pad 1: v[b,ch,y,x]
        int id = e - 882;              // [0,128)
        int b = id >> 6, ch = id & 63;
        float w[9];
#pragma unroll
        for (int i = 0; i < 9; i++) w[i] = wv[ch * 9 + i];
        float bias = bv[ch];
        const float* xp = x + (b * 64 + ch) * 441;
        for (int p = threadIdx.x; p < 441; p += blockDim.x) {
            int y = p / 21, xx = p - y * 21;
            float acc = bias;
#pragma unroll
            for (int dy = 0; dy < 3; dy++) {
                int yy = y + dy - 1;
                if (yy < 0 || yy >= 21) continue;
#pragma unroll
                for (int dx = 0; dx < 3; dx++) {
                    int xx2 = xx + dx - 1;
                    if (xx2 < 0 || xx2 >= 21) continue;
                    acc += xp[yy * 21 + xx2] * w[dy * 3 + dx];
                }
            }
            g_v[id * 441 + p] = acc;
        }
    }
}

// ---------------------------------------------------------------------------
// Kernel 2: per (b, g, c-half of 32): gather kq -> att1(25x50) -> BN/ReLU ->
//           logits(441x25 via SMEM-staged w2) -> softmax(d) -> value dot -> out
// ---------------------------------------------------------------------------
#define NT 512
// SMEM floats: w1s 1252 | kqs 1600 | r1 800 | w2s 11028 | logits 14112 |
//              red 512 | cmax 32 | csum 32
#define SM_FLOATS (1252 + 1600 + 800 + 11028 + 14112 + 512 + 32 + 32)

__global__ __launch_bounds__(NT) void main_kernel(
                            const float* __restrict__ x,
                            const float* __restrict__ w1,
                            const float* __restrict__ bng,
                            const float* __restrict__ bnb,
                            const float* __restrict__ bnm,
                            const float* __restrict__ bnv,
                            const float* __restrict__ w2,
                            const float* __restrict__ b2,
                            float* __restrict__ out) {
    extern __shared__ float sm[];
    float* w1s    = sm;              // 1250 used
    float* kqs    = w1s + 1252;      // 50 x 32
    float* r1     = kqs + 1600;      // 25 x 32 (16B aligned)
    float* w2s    = r1 + 800;        // 441 x 25
    float* logits = w2s + 11028;     // 441 x 32
    float* red    = logits + 14112;  // 16 x 32
    float* cmax   = red + 512;       // 32
    float* csum   = cmax + 32;       // 32

    int bid  = blockIdx.x;
    int b    = bid / 50;
    int g    = (bid >> 1) % 25;
    int half = bid & 1;
    int cbase = half * 32;
    int ph = g / 5, pw = g - ph * 5;
    int tid = threadIdx.x;

    // stage w2[g] (43KB) — independent of gather/att1, overlaps under one sync
    const float* w2g = w2 + g * 11025;
    for (int i = tid; i < 11025; i += NT) w2s[i] = w2g[i];

    // load w1[g]
    for (int i = tid; i < 1250; i += NT) w1s[i] = w1[g * 1250 + i];

    // gather kq[i2][cl]: u = i2*64 + (cbase+cl) -> (s, c, ij)
    for (int idx = tid; idx < 1600; idx += NT) {
        int i2 = idx >> 5, cl = idx & 31;
        int u = i2 * 64 + cbase + cl;
        int s = u / 1600; int rem = u - s * 1600;
        int c = rem / 25; int ij = rem - c * 25;
        int i5 = ij / 5, j5 = ij - i5 * 5;
        int row = 5 * i5 + ph, col = 5 * j5 + pw;
        float v = 0.f;
        if (row < 21 && col < 21) {
            int sp = row * 21 + col;
            v = (s == 0) ? x[(b * 64 + c) * 441 + sp]
                         : g_k1[(b * 441 + sp) * 64 + c];
        }
        kqs[idx] = v;
    }
    __syncthreads();

    // att1 (25 x 32) = w1[g] (25x50) @ kq (50x32), then BN + ReLU
    for (int idx = tid; idx < 800; idx += NT) {
        int o = idx >> 5, cl = idx & 31;
        float acc = 0.f;
#pragma unroll
        for (int i = 0; i < 50; i++) acc += w1s[o * 50 + i] * kqs[i * 32 + cl];
        int go = g * 25 + o;
        float inv = bng[go] * rsqrtf(bnv[go] + 1e-5f);
        acc = (acc - bnm[go]) * inv + bnb[go];
        r1[idx] = fmaxf(acc, 0.f);
    }
    __syncthreads();

    // logits (441 x 32): blocked 4d x 4c, all-SMEM operands
    const float* b2g = b2 + g * 441;
    for (int item = tid; item < 111 * 8; item += NT) {
        int dg = item >> 3, cg = item & 7;
        int d0 = dg * 4;
        int dk0 = d0, dk1 = min(d0 + 1, 440), dk2 = min(d0 + 2, 440), dk3 = min(d0 + 3, 440);
        float a0x=0,a0y=0,a0z=0,a0w=0, a1x=0,a1y=0,a1z=0,a1w=0;
        float a2x=0,a2y=0,a2z=0,a2w=0, a3x=0,a3y=0,a3z=0,a3w=0;
#pragma unroll 5
        for (int o = 0; o < 25; o++) {
            float4 r = *(const float4*)&r1[o * 32 + cg * 4];
            float v0 = w2s[dk0 * 25 + o];
            float v1 = w2s[dk1 * 25 + o];
            float v2 = w2s[dk2 * 25 + o];
            float v3 = w2s[dk3 * 25 + o];
            a0x += v0*r.x; a0y += v0*r.y; a0z += v0*r.z; a0w += v0*r.w;
            a1x += v1*r.x; a1y += v1*r.y; a1z += v1*r.z; a1w += v1*r.w;
            a2x += v2*r.x; a2y += v2*r.y; a2z += v2*r.z; a2w += v2*r.w;
            a3x += v3*r.x; a3y += v3*r.y; a3z += v3*r.z; a3w += v3*r.w;
        }
        int cc = cg * 4;
        {
            float bb = b2g[dk0];
            float* L = &logits[d0 * 32 + cc];
            L[0] = a0x + bb; L[1] = a0y + bb; L[2] = a0z + bb; L[3] = a0w + bb;
        }
        if (d0 + 1 < 441) {
            float bb = b2g[dk1];
            float* L = &logits[(d0 + 1) * 32 + cc];
            L[0] = a1x + bb; L[1] = a1y + bb; L[2] = a1z + bb; L[3] = a1w + bb;
        }
        if (d0 + 2 < 441) {
            float bb = b2g[dk2];
            float* L = &logits[(d0 + 2) * 32 + cc];
            L[0] = a2x + bb; L[1] = a2y + bb; L[2] = a2z + bb; L[3] = a2w + bb;
        }
        if (d0 + 3 < 441) {
            float bb = b2g[dk3];
            float* L = &logits[(d0 + 3) * 32 + cc];
            L[0] = a3x + bb; L[1] = a3y + bb; L[2] = a3z + bb; L[3] = a3w + bb;
        }
    }
    __syncthreads();

    // softmax over d per c-column (max, then sum of exp); 16 rows x 32 cols
    {
        int cl = tid & 31, r = tid >> 5;
        float pm = -1e30f;
        for (int d = r; d < 441; d += 16) pm = fmaxf(pm, logits[d * 32 + cl]);
        red[r * 32 + cl] = pm;
        __syncthreads();
        if (tid < 32) {
            float m = red[tid];
#pragma unroll
            for (int r2 = 1; r2 < 16; r2++) m = fmaxf(m, red[r2 * 32 + tid]);
            cmax[tid] = m;
        }
        __syncthreads();
        float mm = cmax[cl];
        float ps = 0.f;
        for (int d = r; d < 441; d += 16) ps += __expf(logits[d * 32 + cl] - mm);
        __syncthreads();   // red reuse
        red[r * 32 + cl] = ps;
        __syncthreads();
        if (tid < 32) {
            float s2 = 0.f;
#pragma unroll
            for (int r2 = 0; r2 < 16; r2++) s2 += red[r2 * 32 + tid];
            csum[tid] = 1.f / s2;
        }
        __syncthreads();
    }

    // normalize only the live range d in [157, 284) (the only d used below)
    for (int idx = tid; idx < 127 * 32; idx += NT) {
        int d = 157 + (idx >> 5), cl = idx & 31;
        logits[d * 32 + cl] = __expf(logits[d * 32 + cl] - cmax[cl]) * csum[cl];
    }
    __syncthreads();

    // final: for (h,w) with h%5==ph, w%5==pw, h,w in [2,23):
    //   temp = sum_t v[b,t,h-4,w-4] * A[d=220-c+t], out = temp + k1_pad, cropped
    int hl[5], wl[5]; int nh = 0, nw = 0;
    for (int h = ph; h < 23; h += 5) if (h >= 2) hl[nh++] = h;
    for (int w = pw; w < 23; w += 5) if (w >= 2) wl[nw++] = w;
    int npos = nh * nw;
    for (int item = tid; item < npos * 32; item += NT) {
        int p = item >> 5, cl = item & 31;
        int h = hl[p / nw], w = wl[p % nw];
        int c = cbase + cl;
        float acc = 0.f;
        if (h >= 4 && w >= 4) {
            const float* vp = g_v + (b * 64) * 441 + (h - 4) * 21 + (w - 4);
            const float* lp = logits + (220 - c) * 32 + cl;
#pragma unroll 8
            for (int t = 0; t < 64; t++)
                acc += vp[t * 441] * lp[t * 32];
        }
        if (h < 21 && w < 21) acc += g_k1[(b * 441 + h * 21 + w) * 64 + c];
        out[((b * 64 + c) * 21 + (h - 2)) * 21 + (w - 2)] = acc;
    }
}

extern "C" void kernel_launch(void* const* d_in, const int* in_sizes, int n_in,
                              void* d_out, int out_size) {
    const float* x   = (const float*)d_in[0];
    const float* wk  = (const float*)d_in[1];
    const float* bk  = (const float*)d_in[2];
    const float* w1  = (const float*)d_in[3];
    const float* bng = (const float*)d_in[4];
    const float* bnb = (const float*)d_in[5];
    const float* bnm = (const float*)d_in[6];
    const float* bnv = (const float*)d_in[7];
    const float* w2  = (const float*)d_in[8];
    const float* b2  = (const float*)d_in[9];
    const float* wv  = (const float*)d_in[10];
    const float* bv  = (const float*)d_in[11];
    float* out = (float*)d_out;

    cudaFuncSetAttribute(main_kernel, cudaFuncAttributeMaxDynamicSharedMemorySize,
                         SM_FLOATS * (int)sizeof(float));

    prep_kernel<<<1010, 128>>>(x, wk, bk, wv, bv);
    main_kernel<<<100, NT, SM_FLOATS * (int)sizeof(float)>>>(
        x, w1, bng, bnb, bnm, bnv, w2, b2, out);
}

// round 4
// speedup vs baseline: 1.2621x; 1.0092x over previous
#include <cuda_runtime.h>

// Scratch (device globals — no allocations allowed)
__device__ float g_k1[2 * 441 * 64];   // [b*441+d][c]
__device__ float g_v [2 * 64 * 441];   // [b*64+c][21*21]

// ---------------------------------------------------------------------------
// Kernel 1: k1 depthwise conv1d (effective 64 taps) + depthwise 3x3 conv for v
// ---------------------------------------------------------------------------
__global__ void prep_kernel(const float* __restrict__ x,
                            const float* __restrict__ wk,
                            const float* __restrict__ bk,
                            const float* __restrict__ wv,
                            const float* __restrict__ bv) {
    int e = blockIdx.x;
    if (e < 882) {
        // k1[b,d,c] = bk[d] + sum_t x[b,t,d] * wk[d, t + 220 - c]
        int b = e / 441, d = e - b * 441;
        __shared__ float xs[64];
        __shared__ float wks[128];   // wk[d, 157..283]
        int t = threadIdx.x;
        if (t < 64) xs[t] = x[(b * 64 + t) * 441 + d];
        if (t < 127) wks[t] = wk[d * 441 + 157 + t];
        __syncthreads();
        if (t < 64) {
            float acc = bk[d];
#pragma unroll
            for (int tt = 0; tt < 64; tt++)
                acc += xs[tt] * wks[tt + 63 - t];   // (tt+220-t) - 157
            g_k1[e * 64 + t] = acc;
        }
    } else {
        // depthwise 3x3 conv, pad 1: v[b,ch,y,x]
        int id = e - 882;              // [0,128)
        int b = id >> 6, ch = id & 63;
        float w[9];
#pragma unroll
        for (int i = 0; i < 9; i++) w[i] = wv[ch * 9 + i];
        float bias = bv[ch];
        const float* xp = x + (b * 64 + ch) * 441;
        for (int p = threadIdx.x; p < 441; p += blockDim.x) {
            int y = p / 21, xx = p - y * 21;
            float acc = bias;
#pragma unroll
            for (int dy = 0; dy < 3; dy++) {
                int yy = y + dy - 1;
                if (yy < 0 || yy >= 21) continue;
#pragma unroll
                for (int dx = 0; dx < 3; dx++) {
                    int xx2 = xx + dx - 1;
                    if (xx2 < 0 || xx2 >= 21) continue;
                    acc += xp[yy * 21 + xx2] * w[dy * 3 + dx];
                }
            }
            g_v[id * 441 + p] = acc;
        }
    }
}

// ---------------------------------------------------------------------------
// Kernel 2: per (b, g, c-half of 32): gather kq -> att1(25x50) -> BN/ReLU ->
//           logits(441x25 via SMEM w2) -> softmax (norm folded) -> value dot
// ---------------------------------------------------------------------------
#define NT 1024
// SMEM floats: w1s 1252 | kqs 1600 | r1 800 | w2s 11028 | logits 14112 |
//              red 1024 | cmax 32 | csum 32
#define SM_FLOATS (1252 + 1600 + 800 + 11028 + 14112 + 1024 + 32 + 32)

__global__ __launch_bounds__(NT) void main_kernel(
                            const float* __restrict__ x,
                            const float* __restrict__ w1,
                            const float* __restrict__ bng,
                            const float* __restrict__ bnb,
                            const float* __restrict__ bnm,
                            const float* __restrict__ bnv,
                            const float* __restrict__ w2,
                            const float* __restrict__ b2,
                            float* __restrict__ out) {
    extern __shared__ float sm[];
    float* w1s    = sm;              // 1250 used
    float* kqs    = w1s + 1252;      // 50 x 32
    float* r1     = kqs + 1600;      // 25 x 32 (16B aligned)
    float* w2s    = r1 + 800;        // 441 x 25 (+pad)
    float* logits = w2s + 11028;     // 441 x 32
    float* red    = logits + 14112;  // 32 x 32
    float* cmax   = red + 1024;      // 32
    float* csum   = cmax + 32;       // 32

    int bid  = blockIdx.x;
    int b    = bid / 50;
    int g    = (bid >> 1) % 25;
    int half = bid & 1;
    int cbase = half * 32;
    int ph = g / 5, pw = g - ph * 5;
    int tid = threadIdx.x;

    // stage w2[g] (43KB), scalar coalesced (base only 4B-aligned for odd g)
    {
        const float* src = w2 + g * 11025;
        for (int i = tid; i < 11025; i += NT) w2s[i] = src[i];
    }

    // load w1[g]
    for (int i = tid; i < 1250; i += NT) w1s[i] = w1[g * 1250 + i];

    // gather kq[i2][cl]: u = i2*64 + (cbase+cl) -> (s, c, ij)
    for (int idx = tid; idx < 1600; idx += NT) {
        int i2 = idx >> 5, cl = idx & 31;
        int u = i2 * 64 + cbase + cl;
        int s = u / 1600; int rem = u - s * 1600;
        int c = rem / 25; int ij = rem - c * 25;
        int i5 = ij / 5, j5 = ij - i5 * 5;
        int row = 5 * i5 + ph, col = 5 * j5 + pw;
        float v = 0.f;
        if (row < 21 && col < 21) {
            int sp = row * 21 + col;
            v = (s == 0) ? x[(b * 64 + c) * 441 + sp]
                         : g_k1[(b * 441 + sp) * 64 + c];
        }
        kqs[idx] = v;
    }
    __syncthreads();

    // att1 (25 x 32) = w1[g] (25x50) @ kq (50x32), then BN + ReLU
    if (tid < 800) {
        int o = tid >> 5, cl = tid & 31;
        float acc = 0.f;
#pragma unroll
        for (int i = 0; i < 50; i++) acc += w1s[o * 50 + i] * kqs[i * 32 + cl];
        int go = g * 25 + o;
        float inv = bng[go] * rsqrtf(bnv[go] + 1e-5f);
        acc = (acc - bnm[go]) * inv + bnb[go];
        r1[tid] = fmaxf(acc, 0.f);
    }
    __syncthreads();

    // logits (441 x 32): blocked 4d x 4c, all-SMEM operands; 888 items
    const float* b2g = b2 + g * 441;
    if (tid < 888) {
        int dg = tid >> 3, cg = tid & 7;
        int d0 = dg * 4;
        int dk0 = d0, dk1 = min(d0 + 1, 440), dk2 = min(d0 + 2, 440), dk3 = min(d0 + 3, 440);
        float a0x=0,a0y=0,a0z=0,a0w=0, a1x=0,a1y=0,a1z=0,a1w=0;
        float a2x=0,a2y=0,a2z=0,a2w=0, a3x=0,a3y=0,a3z=0,a3w=0;
#pragma unroll 5
        for (int o = 0; o < 25; o++) {
            float4 r = *(const float4*)&r1[o * 32 + cg * 4];
            float v0 = w2s[dk0 * 25 + o];
            float v1 = w2s[dk1 * 25 + o];
            float v2 = w2s[dk2 * 25 + o];
            float v3 = w2s[dk3 * 25 + o];
            a0x += v0*r.x; a0y += v0*r.y; a0z += v0*r.z; a0w += v0*r.w;
            a1x += v1*r.x; a1y += v1*r.y; a1z += v1*r.z; a1w += v1*r.w;
            a2x += v2*r.x; a2y += v2*r.y; a2z += v2*r.z; a2w += v2*r.w;
            a3x += v3*r.x; a3y += v3*r.y; a3z += v3*r.z; a3w += v3*r.w;
        }
        int cc = cg * 4;
        {
            float bb = b2g[dk0];
            float* L = &logits[d0 * 32 + cc];
            L[0] = a0x + bb; L[1] = a0y + bb; L[2] = a0z + bb; L[3] = a0w + bb;
        }
        if (d0 + 1 < 441) {
            float bb = b2g[dk1];
            float* L = &logits[(d0 + 1) * 32 + cc];
            L[0] = a1x + bb; L[1] = a1y + bb; L[2] = a1z + bb; L[3] = a1w + bb;
        }
        if (d0 + 2 < 441) {
            float bb = b2g[dk2];
            float* L = &logits[(d0 + 2) * 32 + cc];
            L[0] = a2x + bb; L[1] = a2y + bb; L[2] = a2z + bb; L[3] = a2w + bb;
        }
        if (d0 + 3 < 441) {
            float bb = b2g[dk3];
            float* L = &logits[(d0 + 3) * 32 + cc];
            L[0] = a3x + bb; L[1] = a3y + bb; L[2] = a3z + bb; L[3] = a3w + bb;
        }
    }
    __syncthreads();

    // softmax over d per c-column; 32 rows x 32 cols; exp stored in-place,
    // 1/sum applied in the final dot
    {
        int cl = tid & 31, r = tid >> 5;
        float pm = -1e30f;
        for (int d = r; d < 441; d += 32) pm = fmaxf(pm, logits[d * 32 + cl]);
        red[r * 32 + cl] = pm;
        __syncthreads();
        if (tid < 32) {
            float m = red[tid];
#pragma unroll
            for (int r2 = 1; r2 < 32; r2++) m = fmaxf(m, red[r2 * 32 + tid]);
            cmax[tid] = m;
        }
        __syncthreads();
        float mm = cmax[cl];
        float ps = 0.f;
        for (int d = r; d < 441; d += 32) {
            float e = __expf(logits[d * 32 + cl] - mm);
            logits[d * 32 + cl] = e;
            ps += e;
        }
        __syncthreads();   // red reuse
        red[r * 32 + cl] = ps;
        __syncthreads();
        if (tid < 32) {
            float s2 = 0.f;
#pragma unroll
            for (int r2 = 0; r2 < 32; r2++) s2 += red[r2 * 32 + tid];
            csum[tid] = 1.f / s2;
        }
        __syncthreads();
    }

    // final: for (h,w) with h%5==ph, w%5==pw, h,w in [2,23):
    //   temp = (sum_t v[b,t,h-4,w-4] * e[d=220-c+t]) * (1/sum), out = temp + k1
    int hl[5], wl[5]; int nh = 0, nw = 0;
    for (int h = ph; h < 23; h += 5) if (h >= 2) hl[nh++] = h;
    for (int w = pw; w < 23; w += 5) if (w >= 2) wl[nw++] = w;
    int npos = nh * nw;
    if (tid < npos * 32) {
        int p = tid >> 5, cl = tid & 31;
        int h = hl[p / nw], w = wl[p % nw];
        int c = cbase + cl;
        float acc = 0.f;
        if (h >= 4 && w >= 4) {
            const float* vp = g_v + (b * 64) * 441 + (h - 4) * 21 + (w - 4);
            const float* lp = logits + (220 - c) * 32 + cl;
#pragma unroll 8
            for (int t = 0; t < 64; t++)
                acc += vp[t * 441] * lp[t * 32];
        }
        acc *= csum[cl];
        if (h < 21 && w < 21) acc += g_k1[(b * 441 + h * 21 + w) * 64 + c];
        out[((b * 64 + c) * 21 + (h - 2)) * 21 + (w - 2)] = acc;
    }
}

extern "C" void kernel_launch(void* const* d_in, const int* in_sizes, int n_in,
                              void* d_out, int out_size) {
    const float* x   = (const float*)d_in[0];
    const float* wk  = (const float*)d_in[1];
    const float* bk  = (const float*)d_in[2];
    const float* w1  = (const float*)d_in[3];
    const float* bng = (const float*)d_in[4];
    const float* bnb = (const float*)d_in[5];
    const float* bnm = (const float*)d_in[6];
    const float* bnv = (const float*)d_in[7];
    const float* w2  = (const float*)d_in[8];
    const float* b2  = (const float*)d_in[9];
    const float* wv  = (const float*)d_in[10];
    const float* bv  = (const float*)d_in[11];
    float* out = (float*)d_out;

    cudaFuncSetAttribute(main_kernel, cudaFuncAttributeMaxDynamicSharedMemorySize,
                         SM_FLOATS * (int)sizeof(float));

    prep_kernel<<<1010, 128>>>(x, wk, bk, wv, bv);
    main_kernel<<<100, NT, SM_FLOATS * (int)sizeof(float)>>>(
        x, w1, bng, bnb, bnm, bnv, w2, b2, out);
}

// round 5
// speedup vs baseline: 1.3320x; 1.0553x over previous
#include <cuda_runtime.h>

// Scratch (device globals — no allocations allowed)
__device__ float g_k1[2 * 441 * 64];   // [b*441+d][c]
__device__ float g_v [2 * 64 * 441];   // [b*64+c][21*21]

// ---------------------------------------------------------------------------
// Kernel 1: k1 depthwise conv1d (effective 64 taps) + depthwise 3x3 conv for v
// ---------------------------------------------------------------------------
__global__ void prep_kernel(const float* __restrict__ x,
                            const float* __restrict__ wk,
                            const float* __restrict__ bk,
                            const float* __restrict__ wv,
                            const float* __restrict__ bv) {
    int e = blockIdx.x;
    if (e < 882) {
        // k1[b,d,c] = bk[d] + sum_t x[b,t,d] * wk[d, t + 220 - c]
        int b = e / 441, d = e - b * 441;
        __shared__ float xs[64];
        __shared__ float wks[128];   // wk[d, 157..283]
        int t = threadIdx.x;
        if (t < 64) xs[t] = x[(b * 64 + t) * 441 + d];
        if (t < 127) wks[t] = wk[d * 441 + 157 + t];
        __syncthreads();
        if (t < 64) {
            float acc = bk[d];
#pragma unroll
            for (int tt = 0; tt < 64; tt++)
                acc += xs[tt] * wks[tt + 63 - t];   // (tt+220-t) - 157
            g_k1[e * 64 + t] = acc;
        }
    } else {
        // depthwise 3x3 conv, pad 1: v[b,ch,y,x]
        int id = e - 882;              // [0,128)
        int b = id >> 6, ch = id & 63;
        float w[9];
#pragma unroll
        for (int i = 0; i < 9; i++) w[i] = wv[ch * 9 + i];
        float bias = bv[ch];
        const float* xp = x + (b * 64 + ch) * 441;
        for (int p = threadIdx.x; p < 441; p += blockDim.x) {
            int y = p / 21, xx = p - y * 21;
            float acc = bias;
#pragma unroll
            for (int dy = 0; dy < 3; dy++) {
                int yy = y + dy - 1;
                if (yy < 0 || yy >= 21) continue;
#pragma unroll
                for (int dx = 0; dx < 3; dx++) {
                    int xx2 = xx + dx - 1;
                    if (xx2 < 0 || xx2 >= 21) continue;
                    acc += xp[yy * 21 + xx2] * w[dy * 3 + dx];
                }
            }
            g_v[id * 441 + p] = acc;
        }
    }
}

// ---------------------------------------------------------------------------
// Kernel 2: per (b, g, c-quarter of 16): gather kq -> att1 -> BN/ReLU ->
//           logits(441x16, SMEM w2) -> softmax (warp-red, norm folded) -> dot
// Grid 200, NT 512, ~84KB smem -> 2 blocks/SM
// ---------------------------------------------------------------------------
#define NT 512
#define NC 16
// SMEM floats: w1s 1252 | kqs 800 | r1 400 | w2s 11028 | logits 7056 |
//              red 512 | cmax 16 | csum 16
#define SM_FLOATS (1252 + 800 + 400 + 11028 + 7056 + 512 + 16 + 16)

__global__ __launch_bounds__(NT, 2) void main_kernel(
                            const float* __restrict__ x,
                            const float* __restrict__ w1,
                            const float* __restrict__ bng,
                            const float* __restrict__ bnb,
                            const float* __restrict__ bnm,
                            const float* __restrict__ bnv,
                            const float* __restrict__ w2,
                            const float* __restrict__ b2,
                            float* __restrict__ out) {
    extern __shared__ float sm[];
    float* w1s    = sm;              // 1250 used
    float* kqs    = w1s + 1252;      // 50 x 16
    float* r1     = kqs + 800;       // 25 x 16 (16B aligned)
    float* w2s    = r1 + 400;        // 441 x 25 (+pad)
    float* logits = w2s + 11028;     // 441 x 16
    float* red    = logits + 7056;   // 32 x 16
    float* cmax   = red + 512;       // 16
    float* csum   = cmax + 16;       // 16

    int bid  = blockIdx.x;
    int b    = bid / 100;
    int rem  = bid - b * 100;
    int g    = rem >> 2;
    int q    = rem & 3;
    int cbase = q * NC;
    int ph = g / 5, pw = g - ph * 5;
    int tid = threadIdx.x;

    // stage w2[g] (43KB), scalar coalesced (base only 4B-aligned for odd g)
    {
        const float* src = w2 + g * 11025;
        for (int i = tid; i < 11025; i += NT) w2s[i] = src[i];
    }

    // load w1[g]
    for (int i = tid; i < 1250; i += NT) w1s[i] = w1[g * 1250 + i];

    // gather kq[i2][cl]: u = i2*64 + (cbase+cl) -> (s, c, ij)
    for (int idx = tid; idx < 800; idx += NT) {
        int i2 = idx >> 4, cl = idx & 15;
        int u = i2 * 64 + cbase + cl;
        int s = u / 1600; int rm = u - s * 1600;
        int c = rm / 25; int ij = rm - c * 25;
        int i5 = ij / 5, j5 = ij - i5 * 5;
        int row = 5 * i5 + ph, col = 5 * j5 + pw;
        float v = 0.f;
        if (row < 21 && col < 21) {
            int sp = row * 21 + col;
            v = (s == 0) ? x[(b * 64 + c) * 441 + sp]
                         : g_k1[(b * 441 + sp) * 64 + c];
        }
        kqs[idx] = v;
    }
    __syncthreads();

    // att1 (25 x 16) = w1[g] (25x50) @ kq (50x16), then BN + ReLU
    if (tid < 400) {
        int o = tid >> 4, cl = tid & 15;
        float acc = 0.f;
#pragma unroll
        for (int i = 0; i < 50; i++) acc += w1s[o * 50 + i] * kqs[i * NC + cl];
        int go = g * 25 + o;
        float inv = bng[go] * rsqrtf(bnv[go] + 1e-5f);
        acc = (acc - bnm[go]) * inv + bnb[go];
        r1[tid] = fmaxf(acc, 0.f);
    }
    __syncthreads();

    // logits (441 x 16): blocked 4d x 4c, all-SMEM operands; 444 items
    const float* b2g = b2 + g * 441;
    if (tid < 444) {
        int dg = tid >> 2, cg = tid & 3;
        int d0 = dg * 4;
        int dk0 = d0, dk1 = min(d0 + 1, 440), dk2 = min(d0 + 2, 440), dk3 = min(d0 + 3, 440);
        float a0x=0,a0y=0,a0z=0,a0w=0, a1x=0,a1y=0,a1z=0,a1w=0;
        float a2x=0,a2y=0,a2z=0,a2w=0, a3x=0,a3y=0,a3z=0,a3w=0;
#pragma unroll 5
        for (int o = 0; o < 25; o++) {
            float4 r = *(const float4*)&r1[o * NC + cg * 4];
            float v0 = w2s[dk0 * 25 + o];
            float v1 = w2s[dk1 * 25 + o];
            float v2 = w2s[dk2 * 25 + o];
            float v3 = w2s[dk3 * 25 + o];
            a0x += v0*r.x; a0y += v0*r.y; a0z += v0*r.z; a0w += v0*r.w;
            a1x += v1*r.x; a1y += v1*r.y; a1z += v1*r.z; a1w += v1*r.w;
            a2x += v2*r.x; a2y += v2*r.y; a2z += v2*r.z; a2w += v2*r.w;
            a3x += v3*r.x; a3y += v3*r.y; a3z += v3*r.z; a3w += v3*r.w;
        }
        int cc = cg * 4;
        {
            float bb = b2g[dk0];
            float* L = &logits[d0 * NC + cc];
            L[0] = a0x + bb; L[1] = a0y + bb; L[2] = a0z + bb; L[3] = a0w + bb;
        }
        if (d0 + 1 < 441) {
            float bb = b2g[dk1];
            float* L = &logits[(d0 + 1) * NC + cc];
            L[0] = a1x + bb; L[1] = a1y + bb; L[2] = a1z + bb; L[3] = a1w + bb;
        }
        if (d0 + 2 < 441) {
            float bb = b2g[dk2];
            float* L = &logits[(d0 + 2) * NC + cc];
            L[0] = a2x + bb; L[1] = a2y + bb; L[2] = a2z + bb; L[3] = a2w + bb;
        }
        if (d0 + 3 < 441) {
            float bb = b2g[dk3];
            float* L = &logits[(d0 + 3) * NC + cc];
            L[0] = a3x + bb; L[1] = a3y + bb; L[2] = a3z + bb; L[3] = a3w + bb;
        }
    }
    __syncthreads();

    // softmax over d per c-column; 32 rows x 16 cols; warp-shuffle block
    // reductions; exp stored in-place, 1/sum applied in the final dot
    {
        int cl = tid & 15, r = tid >> 4;
        int wid = tid >> 5, lane = tid & 31;
        float pm = -1e30f;
        for (int d = r; d < 441; d += 32) pm = fmaxf(pm, logits[d * NC + cl]);
        red[r * NC + cl] = pm;
        __syncthreads();
        if (wid < 16) {            // warp wid reduces column wid
            float v = red[lane * NC + wid];
#pragma unroll
            for (int off = 16; off; off >>= 1)
                v = fmaxf(v, __shfl_xor_sync(0xFFFFFFFFu, v, off));
            if (lane == 0) cmax[wid] = v;
        }
        __syncthreads();
        float mm = cmax[cl];
        float ps = 0.f;
        for (int d = r; d < 441; d += 32) {
            float e = __expf(logits[d * NC + cl] - mm);
            logits[d * NC + cl] = e;
            ps += e;
        }
        __syncthreads();   // red reuse
        red[r * NC + cl] = ps;
        __syncthreads();
        if (wid < 16) {
            float v = red[lane * NC + wid];
#pragma unroll
            for (int off = 16; off; off >>= 1)
                v += __shfl_xor_sync(0xFFFFFFFFu, v, off);
            if (lane == 0) csum[wid] = 1.f / v;
        }
        __syncthreads();
    }

    // final: for (h,w) with h%5==ph, w%5==pw, h,w in [2,23):
    //   temp = (sum_t v[b,t,h-4,w-4] * e[d=220-c+t]) * (1/sum), out = temp + k1
    int hl[5], wl[5]; int nh = 0, nw = 0;
    for (int h = ph; h < 23; h += 5) if (h >= 2) hl[nh++] = h;
    for (int w = pw; w < 23; w += 5) if (w >= 2) wl[nw++] = w;
    int npos = nh * nw;
    if (tid < npos * NC) {
        int p = tid >> 4, cl = tid & 15;
        int h = hl[p / nw], w = wl[p % nw];
        int c = cbase + cl;
        float acc = 0.f;
        if (h >= 4 && w >= 4) {
            const float* vp = g_v + (b * 64) * 441 + (h - 4) * 21 + (w - 4);
            const float* lp = logits + (220 - c) * NC + cl;
#pragma unroll 8
            for (int t = 0; t < 64; t++)
                acc += vp[t * 441] * lp[t * NC];
        }
        acc *= csum[cl];
        if (h < 21 && w < 21) acc += g_k1[(b * 441 + h * 21 + w) * 64 + c];
        out[((b * 64 + c) * 21 + (h - 2)) * 21 + (w - 2)] = acc;
    }
}

extern "C" void kernel_launch(void* const* d_in, const int* in_sizes, int n_in,
                              void* d_out, int out_size) {
    const float* x   = (const float*)d_in[0];
    const float* wk  = (const float*)d_in[1];
    const float* bk  = (const float*)d_in[2];
    const float* w1  = (const float*)d_in[3];
    const float* bng = (const float*)d_in[4];
    const float* bnb = (const float*)d_in[5];
    const float* bnm = (const float*)d_in[6];
    const float* bnv = (const float*)d_in[7];
    const float* w2  = (const float*)d_in[8];
    const float* b2  = (const float*)d_in[9];
    const float* wv  = (const float*)d_in[10];
    const float* bv  = (const float*)d_in[11];
    float* out = (float*)d_out;

    cudaFuncSetAttribute(main_kernel, cudaFuncAttributeMaxDynamicSharedMemorySize,
                         SM_FLOATS * (int)sizeof(float));

    prep_kernel<<<1010, 128>>>(x, wk, bk, wv, bv);
    main_kernel<<<200, NT, SM_FLOATS * (int)sizeof(float)>>>(
        x, w1, bng, bnb, bnm, bnv, w2, b2, out);
}